// round 13
// baseline (speedup 1.0000x reference)
#include <cuda_runtime.h>
#include <cuda_fp16.h>
#include <cstdint>

#define BATCH 128
#define NN    64
#define C1    256
#define C2    96
#define PW    264         // smem pitch in halves (528B rows, conflict-free for ldmatrix)
#define GRID  148
#define THREADS 256

// ---------------- global scratch ---------------------------------------------
__device__ float  g_P[BATCH * NN * C1];
__device__ float  g_Q[BATCH * NN * C1];
__device__ __half g_B1[256 * PW];           // W1^T [n=256][k=256] pitch 264
__device__ __half g_B2[96 * PW];            // W2^T [n=96][k=256] pitch 264
__device__ float  g_AGG[BATCH * NN * C2];
__device__ float  g_vec[C1 + C1 + 128];     // w0d | b1 | b2

__device__ __forceinline__ float lrelu(float v) { return v > 0.f ? v : 0.2f * v; }

#define CP_ASYNC16(smaddr, gptr) \
    asm volatile("cp.async.cg.shared.global [%0], [%1], 16;" :: "r"(smaddr), "l"(gptr))
#define CP_COMMIT() asm volatile("cp.async.commit_group;")
#define CP_WAIT0()  asm volatile("cp.async.wait_group 0;" ::: "memory")

__device__ __forceinline__ void hmma(float* c, const uint32_t* a, const uint32_t* b) {
    asm volatile(
        "mma.sync.aligned.m16n8k16.row.col.f32.f16.f16.f32 "
        "{%0,%1,%2,%3}, {%4,%5,%6,%7}, {%8,%9}, {%0,%1,%2,%3};"
        : "+f"(c[0]), "+f"(c[1]), "+f"(c[2]), "+f"(c[3])
        : "r"(a[0]), "r"(a[1]), "r"(a[2]), "r"(a[3]), "r"(b[0]), "r"(b[1]));
}

#define LDSM4(R0, R1, R2, R3, ADDR) \
    asm volatile("ldmatrix.sync.aligned.m8n8.x4.shared.b16 {%0,%1,%2,%3}, [%4];" \
        : "=r"(R0), "=r"(R1), "=r"(R2), "=r"(R3) : "r"(ADDR))
#define LDSM2(R0, R1, ADDR) \
    asm volatile("ldmatrix.sync.aligned.m8n8.x2.shared.b16 {%0,%1}, [%2];" \
        : "=r"(R0), "=r"(R1) : "r"(ADDR))

// ---------------- kernel: P/Q precompute (fp32) ------------------------------
__global__ __launch_bounds__(256) void pq_kernel(
    const float* __restrict__ x, const float* __restrict__ W0,
    const float* __restrict__ b0)
{
    __shared__ float xs[16 * 64];
    const int r0 = blockIdx.x * 16;
    const int tid = threadIdx.x;
    ((float4*)xs)[tid] = ((const float4*)(x + (size_t)r0 * 64))[tid];
    __syncthreads();
    const int c = tid;
    float accP[16], accQ[16];
#pragma unroll
    for (int r = 0; r < 16; r++) { accP[r] = 0.f; accQ[r] = 0.f; }
#pragma unroll 4
    for (int f = 0; f < 64; f++) {
        float wp = W0[f * C1 + c];
        float wq = W0[(64 + f) * C1 + c];
#pragma unroll
        for (int r = 0; r < 16; r++) {
            float xv = xs[r * 64 + f];
            accP[r] = fmaf(xv, wp, accP[r]);
            accQ[r] = fmaf(xv, wq, accQ[r]);
        }
    }
    float bias = b0[c];
#pragma unroll
    for (int r = 0; r < 16; r++) {
        g_P[(size_t)(r0 + r) * C1 + c] = accP[r] + bias;
        g_Q[(size_t)(r0 + r) * C1 + c] = accQ[r];
    }
}

// ---------------- kernel: weight fp16 transpose-pack (pitch 264) -------------
__global__ __launch_bounds__(256) void prep_w(
    const float* __restrict__ W1, const float* __restrict__ W2)
{
    int idx = blockIdx.x * 256 + threadIdx.x;
    if (idx < 65536) {                      // B1: n=idx>>8, k=idx&255
        int n = idx >> 8, k = idx & 255;
        g_B1[n * PW + k] = __float2half_rn(W1[(size_t)k * C1 + n]);
    } else if (idx - 65536 < 24576) {       // B2
        int p = idx - 65536;
        int n = p >> 8, k = p & 255;
        g_B2[n * PW + k] = __float2half_rn(W2[(size_t)k * C2 + n]);
    }
}

__global__ void prep_vec(const float* __restrict__ W0,
                         const float* __restrict__ b1,
                         const float* __restrict__ b2) {
    int t = threadIdx.x;
    g_vec[t] = W0[128 * C1 + t];
    g_vec[C1 + t] = b1[t];
    if (t < C2) g_vec[2 * C1 + t] = b2[t];
}

// ---------------- main persistent kernel (weights resident in smem) ----------
#define OFF_A    0                          // 64 x 264 halves = 33792
#define OFF_B1   33792                      // 256 x 264 halves = 135168
#define OFF_B2   168960                     // 96 x 264 halves = 50688
#define OFF_PV   219648                     // 1024
#define OFF_W0   220672                     // 1024
#define OFF_B1S  221696                     // 1024
#define OFF_B2S  222720                     // 512
#define OFF_DIST 223232                     // 256
#define OFF_RED  223488                     // 768
#define SMEM_SZ  224256

__global__ void __launch_bounds__(THREADS, 1) mp_main(const float* __restrict__ x)
{
    extern __shared__ __align__(16) unsigned char sm[];
    const unsigned smb = (unsigned)__cvta_generic_to_shared(sm);
    const int tid = threadIdx.x;
    const int w = tid >> 5, lane = tid & 31;
    const int wm = w & 1, wn = w >> 1;      // 2 m-halves x 4 n-groups

    __half* Ah  = (__half*)(sm + OFF_A);
    float* pv   = (float*)(sm + OFF_PV);
    float* w0s  = (float*)(sm + OFF_W0);
    float* b1s  = (float*)(sm + OFF_B1S);
    float* b2s  = (float*)(sm + OFF_B2S);
    float* dst_ = (float*)(sm + OFF_DIST);
    float* red  = (float*)(sm + OFF_RED);

    // ---- load all weights into smem once (cp.async) ----
    {
        const char* g1 = (const char*)g_B1;
        for (int q = tid * 16; q < 135168; q += THREADS * 16)
            CP_ASYNC16(smb + OFF_B1 + q, g1 + q);
        const char* g2 = (const char*)g_B2;
        for (int q = tid * 16; q < 50688; q += THREADS * 16)
            CP_ASYNC16(smb + OFF_B2 + q, g2 + q);
        CP_COMMIT();
    }
    // ---- stage small vectors (once) ----
    w0s[tid] = g_vec[tid];
    b1s[tid] = g_vec[C1 + tid];
    if (tid < C2) b2s[tid] = g_vec[2 * C1 + tid];
    CP_WAIT0();
    __syncthreads();

    // ---- ldmatrix lane address components (bytes) ----
    const unsigned aRow = lane & 15;
    const unsigned aK   = (lane >> 4) << 3;
    const unsigned aHB  = smb + OFF_A + ((wm * 32 + aRow) * PW + aK) * 2;
    const unsigned bN   = (lane & 7) + ((lane >> 4) << 3);
    const unsigned bK   = ((lane >> 3) & 1) << 3;
    const unsigned bOff  = (bN * PW + bK) * 2;
    const unsigned bOff2 = ((lane & 7) * PW + (((lane >> 3) & 1) << 3)) * 2;
    const unsigned b1Base = smb + OFF_B1 + wn * (64 * PW * 2);
    const unsigned b2Base = smb + OFF_B2 + wn * (24 * PW * 2);

    for (int node = blockIdx.x; node < BATCH * NN; node += GRID) {
        const int b = node >> 6, i = node & 63;

        // ---- stage pv + distances ----
        pv[tid] = g_P[(size_t)node * C1 + tid];
        if (tid < 64) {
            const float* xi = x + ((size_t)b * 64 + i) * 64;
            const float* xj = x + ((size_t)b * 64 + tid) * 64;
            float s = 0.f;
#pragma unroll
            for (int f = 0; f < 64; f++) {
                float d = xj[f] - xi[f] + 1e-12f;
                s = fmaf(d, d, s);
            }
            dst_[tid] = sqrtf(s);
        }
        __syncthreads();

        // ---- build h0 fp16: 64 x 256 (each thread: quarter row) ----
        {
            int r = tid >> 2, kq = (tid & 3) * 64;
            float dj = dst_[r];
            const float4* q4 = (const float4*)(g_Q + ((size_t)(b * 64 + r)) * 256);
            __half2* ahp = (__half2*)(Ah + r * PW);
#pragma unroll
            for (int g4 = 0; g4 < 16; g4++) {
                int k = kq + g4 * 4;
                float4 q = q4[k >> 2];
                float v0 = lrelu(pv[k + 0] + q.x + dj * w0s[k + 0]);
                float v1 = lrelu(pv[k + 1] + q.y + dj * w0s[k + 1]);
                float v2 = lrelu(pv[k + 2] + q.z + dj * w0s[k + 2]);
                float v3 = lrelu(pv[k + 3] + q.w + dj * w0s[k + 3]);
                ahp[(k >> 1) + 0] = __halves2half2(__float2half_rn(v0), __float2half_rn(v1));
                ahp[(k >> 1) + 1] = __halves2half2(__float2half_rn(v2), __float2half_rn(v3));
            }
        }
        __syncthreads();

        // ======== GEMM1: h1 = lrelu(h0 @ W1 + b1), warp tile 32x64 ========
        float acc[2][8][4];
#pragma unroll
        for (int mf = 0; mf < 2; mf++)
#pragma unroll
            for (int nf = 0; nf < 8; nf++)
#pragma unroll
                for (int e = 0; e < 4; e++) acc[mf][nf][e] = 0.f;

#pragma unroll 4
        for (int kk = 0; kk < 16; kk++) {
            const unsigned kB = kk * 32;    // 16 halves = 32 bytes
            uint32_t ah[2][4];
#pragma unroll
            for (int mf = 0; mf < 2; mf++)
                LDSM4(ah[mf][0], ah[mf][1], ah[mf][2], ah[mf][3],
                      aHB + mf * (16 * PW * 2) + kB);
            uint32_t bf[4][4];
#pragma unroll
            for (int p = 0; p < 4; p++)
                LDSM4(bf[p][0], bf[p][1], bf[p][2], bf[p][3],
                      b1Base + bOff + p * (16 * PW * 2) + kB);
#pragma unroll
            for (int p = 0; p < 4; p++)
#pragma unroll
                for (int q = 0; q < 2; q++) {
                    int nf = 2 * p + q;
                    uint32_t bb[2] = { bf[p][2 * q], bf[p][2 * q + 1] };
#pragma unroll
                    for (int mf = 0; mf < 2; mf++) hmma(acc[mf][nf], ah[mf], bb);
                }
        }
        __syncthreads();

        // ---- h1 epilogue: bias + lrelu, fp16, overwrite A ----
        {
            const int g = lane >> 2, tig = lane & 3;
#pragma unroll
            for (int mf = 0; mf < 2; mf++) {
                int row0 = wm * 32 + mf * 16 + g, row1 = row0 + 8;
#pragma unroll
                for (int nf = 0; nf < 8; nf++) {
                    int col = wn * 64 + nf * 8 + 2 * tig;
                    float ba = b1s[col], bb = b1s[col + 1];
                    *(__half2*)(Ah + row0 * PW + col) = __halves2half2(
                        __float2half_rn(lrelu(acc[mf][nf][0] + ba)),
                        __float2half_rn(lrelu(acc[mf][nf][1] + bb)));
                    *(__half2*)(Ah + row1 * PW + col) = __halves2half2(
                        __float2half_rn(lrelu(acc[mf][nf][2] + ba)),
                        __float2half_rn(lrelu(acc[mf][nf][3] + bb)));
                }
            }
        }
        __syncthreads();

        // ======== GEMM2: h2 = lrelu(h1 @ W2 + b2), warp tile 32x24 ========
        float ac2[2][3][4];
#pragma unroll
        for (int mf = 0; mf < 2; mf++)
#pragma unroll
            for (int nf = 0; nf < 3; nf++)
#pragma unroll
                for (int e = 0; e < 4; e++) ac2[mf][nf][e] = 0.f;

#pragma unroll 4
        for (int kk = 0; kk < 16; kk++) {
            const unsigned kB = kk * 32;
            uint32_t ah[2][4];
#pragma unroll
            for (int mf = 0; mf < 2; mf++)
                LDSM4(ah[mf][0], ah[mf][1], ah[mf][2], ah[mf][3],
                      aHB + mf * (16 * PW * 2) + kB);
            uint32_t bf01[4], bf2[2];
            LDSM4(bf01[0], bf01[1], bf01[2], bf01[3], b2Base + bOff + kB);
            LDSM2(bf2[0], bf2[1], b2Base + 16 * PW * 2 + bOff2 + kB);
#pragma unroll
            for (int nf = 0; nf < 3; nf++) {
                uint32_t bb[2];
                if (nf < 2) { bb[0] = bf01[2 * nf]; bb[1] = bf01[2 * nf + 1]; }
                else        { bb[0] = bf2[0];       bb[1] = bf2[1]; }
#pragma unroll
                for (int mf = 0; mf < 2; mf++) hmma(ac2[mf][nf], ah[mf], bb);
            }
        }

        // ---- reduce over j: bias+lrelu, in-thread + shfl (over g) + cross-warp ----
        {
            const int tig = lane & 3;
            float s[3][2];
#pragma unroll
            for (int nf = 0; nf < 3; nf++) {
                int col = wn * 24 + nf * 8 + 2 * tig;
                float ba = b2s[col], bb = b2s[col + 1];
                s[nf][0] = lrelu(ac2[0][nf][0] + ba) + lrelu(ac2[0][nf][2] + ba)
                         + lrelu(ac2[1][nf][0] + ba) + lrelu(ac2[1][nf][2] + ba);
                s[nf][1] = lrelu(ac2[0][nf][1] + bb) + lrelu(ac2[0][nf][3] + bb)
                         + lrelu(ac2[1][nf][1] + bb) + lrelu(ac2[1][nf][3] + bb);
            }
#pragma unroll
            for (int off = 4; off <= 16; off <<= 1)
#pragma unroll
                for (int nf = 0; nf < 3; nf++) {
                    s[nf][0] += __shfl_xor_sync(0xffffffffu, s[nf][0], off);
                    s[nf][1] += __shfl_xor_sync(0xffffffffu, s[nf][1], off);
                }
            if (lane < 4) {
#pragma unroll
                for (int nf = 0; nf < 3; nf++) {
                    red[wm * 96 + wn * 24 + nf * 8 + 2 * lane]     = s[nf][0];
                    red[wm * 96 + wn * 24 + nf * 8 + 2 * lane + 1] = s[nf][1];
                }
            }
        }
        __syncthreads();
        if (tid < 96)
            g_AGG[(size_t)node * C2 + tid] = red[tid] + red[96 + tid];
        // no extra sync needed: next stage writes (pv/dist) touch different buffers,
        // and the stage-sync orders them before h0 overwrites Ah.
    }
}

// ---------------- node MLP (fp32) --------------------------------------------
__global__ __launch_bounds__(256) void node_kernel(
    const float* __restrict__ x,
    const float* __restrict__ Wn0, const float* __restrict__ bn0,
    const float* __restrict__ Wn1, const float* __restrict__ bn1,
    float* __restrict__ out)
{
    __shared__ float t160[16 * 160];
    __shared__ float zs[16 * 256];
    const int r0 = blockIdx.x * 16;
    const int tid = threadIdx.x;

    for (int idx = tid; idx < 16 * 160; idx += 256) {
        int rr = idx / 160, k = idx - rr * 160;
        t160[idx] = (k < 96) ? g_AGG[(size_t)(r0 + rr) * 96 + k]
                             : x[(size_t)(r0 + rr) * 64 + (k - 96)];
    }
    __syncthreads();
    {
        const int c = tid;
        float acc[16];
        float bb = bn0[c];
#pragma unroll
        for (int r = 0; r < 16; r++) acc[r] = bb;
#pragma unroll 4
        for (int k = 0; k < 160; k++) {
            float wv = Wn0[(size_t)k * 256 + c];
#pragma unroll
            for (int r = 0; r < 16; r++) acc[r] = fmaf(t160[r * 160 + k], wv, acc[r]);
        }
#pragma unroll
        for (int r = 0; r < 16; r++) zs[r * 256 + c] = lrelu(acc[r]);
    }
    __syncthreads();
    for (int pass = 0; pass < 4; pass++) {
        int r = pass * 4 + (tid >> 6), c = tid & 63;
        float a = bn1[c];
#pragma unroll 8
        for (int k = 0; k < 256; k++)
            a = fmaf(zs[r * 256 + k], Wn1[(size_t)k * 64 + c], a);
        out[(size_t)(r0 + r) * 64 + c] = a;
    }
}

// ---------------- launch -----------------------------------------------------
extern "C" void kernel_launch(void* const* d_in, const int* in_sizes, int n_in,
                              void* d_out, int out_size)
{
    const float* x    = (const float*)d_in[0];
    const float* feW0 = (const float*)d_in[1];
    const float* feb0 = (const float*)d_in[2];
    const float* feW1 = (const float*)d_in[3];
    const float* feb1 = (const float*)d_in[4];
    const float* feW2 = (const float*)d_in[5];
    const float* feb2 = (const float*)d_in[6];
    const float* fnW0 = (const float*)d_in[7];
    const float* fnb0 = (const float*)d_in[8];
    const float* fnW1 = (const float*)d_in[9];
    const float* fnb1 = (const float*)d_in[10];
    float* out = (float*)d_out;

    cudaFuncSetAttribute(mp_main, cudaFuncAttributeMaxDynamicSharedMemorySize, SMEM_SZ);

    pq_kernel<<<512, 256>>>(x, feW0, feb0);
    prep_w<<<352, 256>>>(feW1, feW2);
    prep_vec<<<1, 256>>>(feW0, feb1, feb2);
    mp_main<<<GRID, THREADS, SMEM_SZ>>>(x);
    node_kernel<<<512, 256>>>(x, fnW0, fnb0, fnW1, fnb1, out);
}

// round 14
// speedup vs baseline: 1.5262x; 1.5262x over previous
#include <cuda_runtime.h>
#include <cuda_fp16.h>
#include <cstdint>

#define BATCH 128
#define NN    64
#define C1    256
#define C2    96
#define PA    264         // A smem pitch in halves (528B, conflict-free)
#define PB    72          // B smem pitch in halves (144B, 16B-aligned, conflict-free)
#define THREADS 128

// ---------------- global scratch ---------------------------------------------
__device__ float  g_P[BATCH * NN * C1];
__device__ float  g_Q[BATCH * NN * C1];
__device__ __half g_B1[4 * 256 * PB];       // [kchunk64][n=256][k=72pad]
__device__ __half g_B2[4 * 96 * PB];        // [kchunk64][n=96][k=72pad]
__device__ float  g_DIST[BATCH * NN * 64];
__device__ float  g_AGG[BATCH * NN * C2];
__device__ float  g_vec[C1 + C1 + 128];     // w0d | b1 | b2

__device__ __forceinline__ float lrelu(float v) { return v > 0.f ? v : 0.2f * v; }

#define CP_ASYNC16(smaddr, gptr) \
    asm volatile("cp.async.cg.shared.global [%0], [%1], 16;" :: "r"(smaddr), "l"(gptr))
#define CP_COMMIT() asm volatile("cp.async.commit_group;")
#define CP_WAIT0()  asm volatile("cp.async.wait_group 0;" ::: "memory")

__device__ __forceinline__ void hmma(float* c, const uint32_t* a, const uint32_t* b) {
    asm volatile(
        "mma.sync.aligned.m16n8k16.row.col.f32.f16.f16.f32 "
        "{%0,%1,%2,%3}, {%4,%5,%6,%7}, {%8,%9}, {%0,%1,%2,%3};"
        : "+f"(c[0]), "+f"(c[1]), "+f"(c[2]), "+f"(c[3])
        : "r"(a[0]), "r"(a[1]), "r"(a[2]), "r"(a[3]), "r"(b[0]), "r"(b[1]));
}

#define LDSM4(R0, R1, R2, R3, ADDR) \
    asm volatile("ldmatrix.sync.aligned.m8n8.x4.shared.b16 {%0,%1,%2,%3}, [%4];" \
        : "=r"(R0), "=r"(R1), "=r"(R2), "=r"(R3) : "r"(ADDR))
#define LDSM2(R0, R1, ADDR) \
    asm volatile("ldmatrix.sync.aligned.m8n8.x2.shared.b16 {%0,%1}, [%2];" \
        : "=r"(R0), "=r"(R1) : "r"(ADDR))

// ---------------- kernel: P/Q precompute (fp32) ------------------------------
__global__ __launch_bounds__(256) void pq_kernel(
    const float* __restrict__ x, const float* __restrict__ W0,
    const float* __restrict__ b0)
{
    __shared__ float xs[16 * 64];
    const int r0 = blockIdx.x * 16;
    const int tid = threadIdx.x;
    ((float4*)xs)[tid] = ((const float4*)(x + (size_t)r0 * 64))[tid];
    __syncthreads();
    const int c = tid;
    float accP[16], accQ[16];
#pragma unroll
    for (int r = 0; r < 16; r++) { accP[r] = 0.f; accQ[r] = 0.f; }
#pragma unroll 4
    for (int f = 0; f < 64; f++) {
        float wp = W0[f * C1 + c];
        float wq = W0[(64 + f) * C1 + c];
#pragma unroll
        for (int r = 0; r < 16; r++) {
            float xv = xs[r * 64 + f];
            accP[r] = fmaf(xv, wp, accP[r]);
            accQ[r] = fmaf(xv, wq, accQ[r]);
        }
    }
    float bias = b0[c];
#pragma unroll
    for (int r = 0; r < 16; r++) {
        g_P[(size_t)(r0 + r) * C1 + c] = accP[r] + bias;
        g_Q[(size_t)(r0 + r) * C1 + c] = accQ[r];
    }
}

// ---------------- kernel: all-pairs distances per batch ----------------------
__global__ __launch_bounds__(256) void dist_kernel(const float* __restrict__ x)
{
    __shared__ float xs[64 * 64];
    const int b = blockIdx.x;
    const int tid = threadIdx.x;
    for (int t = tid; t < 1024; t += 256)
        ((float4*)xs)[t] = ((const float4*)(x + (size_t)b * 4096))[t];
    __syncthreads();
    for (int p = tid; p < 4096; p += 256) {
        int i = p >> 6, j = p & 63;
        float s = 0.f;
#pragma unroll
        for (int f = 0; f < 64; f++) {
            float d = xs[j * 64 + f] - xs[i * 64 + f] + 1e-12f;
            s = fmaf(d, d, s);
        }
        g_DIST[((size_t)b * 64 + i) * 64 + j] = sqrtf(s);
    }
}

// ---------------- kernel: weight fp16 pack (k64 chunks, PB=72) ---------------
__global__ __launch_bounds__(256) void prep_w(
    const float* __restrict__ W1, const float* __restrict__ W2)
{
    int idx = blockIdx.x * 256 + threadIdx.x;
    if (idx < 65536) {                      // B1: 4 chunks x 256 n x 64 k
        int t = idx >> 14, rem = idx & 16383;
        int n = rem >> 6, k = rem & 63;
        g_B1[(size_t)(t * 256 + n) * PB + k] =
            __float2half_rn(W1[(size_t)(t * 64 + k) * C1 + n]);
    } else if (idx - 65536 < 24576) {       // B2: 4 chunks x 96 n x 64 k
        int p = idx - 65536;
        int t = p / 6144, rem = p % 6144;
        int n = rem >> 6, k = rem & 63;
        g_B2[(size_t)(t * 96 + n) * PB + k] =
            __float2half_rn(W2[(size_t)(t * 64 + k) * C2 + n]);
    }
}

__global__ void prep_vec(const float* __restrict__ W0,
                         const float* __restrict__ b1,
                         const float* __restrict__ b2) {
    int t = threadIdx.x;
    g_vec[t] = W0[128 * C1 + t];
    g_vec[C1 + t] = b1[t];
    if (t < C2) g_vec[2 * C1 + t] = b2[t];
}

// ---------------- main mma.sync kernel (1 node / CTA, 2 CTAs per SM) ---------
#define B1_CHUNK_HALVES (256 * PB)          // 18432
#define B1_CHUNK_BYTES  (B1_CHUNK_HALVES * 2)   // 36864
#define B2_CHUNK_HALVES (96 * PB)           // 6912
#define B2_CHUNK_BYTES  (B2_CHUNK_HALVES * 2)   // 13824
#define BBUF_BYTES      36864
#define OFF_A    0                          // 64 x 264 halves = 33792
#define OFF_B    33792                      // 2 x 36864 = 73728
#define OFF_PV   107520                     // 1024
#define OFF_W0   108544                     // 1024
#define OFF_B1S  109568                     // 1024
#define OFF_B2S  110592                     // 512
#define OFF_DIST 111104                     // 256
#define SMEM_SZ  111360

__global__ void __launch_bounds__(THREADS, 2) mp_main(const float* __restrict__ x)
{
    extern __shared__ __align__(16) unsigned char sm[];
    const unsigned smb = (unsigned)__cvta_generic_to_shared(sm);
    const int tid = threadIdx.x;
    const int w = tid >> 5, lane = tid & 31;
    const int node = blockIdx.x;
    const int b = node >> 6;

    __half* Ah  = (__half*)(sm + OFF_A);
    float* pv   = (float*)(sm + OFF_PV);
    float* w0s  = (float*)(sm + OFF_W0);
    float* b1s  = (float*)(sm + OFF_B1S);
    float* b2s  = (float*)(sm + OFF_B2S);
    float* dst_ = (float*)(sm + OFF_DIST);

    auto loadB = [&](const __half* gsrc, int dstbuf, int bytes) {
        unsigned sb = smb + OFF_B + dstbuf * BBUF_BYTES;
        const char* gp = (const char*)gsrc;
        for (int q = tid * 16; q < bytes; q += THREADS * 16)
            CP_ASYNC16(sb + q, gp + q);
        CP_COMMIT();
    };

    // issue first B1 chunk immediately (overlaps with staging + h0 build)
    loadB(g_B1, 0, B1_CHUNK_BYTES);

    // ---- stage small vectors + dist ----
    {
        pv[tid]        = g_P[(size_t)node * C1 + tid];
        pv[tid + 128]  = g_P[(size_t)node * C1 + tid + 128];
        w0s[tid]       = g_vec[tid];
        w0s[tid + 128] = g_vec[tid + 128];
        b1s[tid]       = g_vec[C1 + tid];
        b1s[tid + 128] = g_vec[C1 + tid + 128];
        if (tid < C2) b2s[tid] = g_vec[2 * C1 + tid];
        if (tid < 64) dst_[tid] = g_DIST[(size_t)node * 64 + tid];
    }
    __syncthreads();

    // ---- build h0 fp16: 64 x 256 (each thread: half a row) ----
    {
        int r = tid >> 1, kq = (tid & 1) * 128;
        float dj = dst_[r];
        const float4* q4 = (const float4*)(g_Q + ((size_t)(b * 64 + r)) * 256);
        __half2* ahp = (__half2*)(Ah + r * PA);
#pragma unroll
        for (int g4 = 0; g4 < 32; g4++) {
            int k = kq + g4 * 4;
            float4 q = q4[k >> 2];
            float v0 = lrelu(pv[k + 0] + q.x + dj * w0s[k + 0]);
            float v1 = lrelu(pv[k + 1] + q.y + dj * w0s[k + 1]);
            float v2 = lrelu(pv[k + 2] + q.z + dj * w0s[k + 2]);
            float v3 = lrelu(pv[k + 3] + q.w + dj * w0s[k + 3]);
            ahp[(k >> 1) + 0] = __halves2half2(__float2half_rn(v0), __float2half_rn(v1));
            ahp[(k >> 1) + 1] = __halves2half2(__float2half_rn(v2), __float2half_rn(v3));
        }
    }

    // ---- ldmatrix lane address components (bytes) ----
    const unsigned aRow = lane & 15;
    const unsigned aK   = (lane >> 4) << 3;
    const unsigned aHB  = smb + OFF_A + (aRow * PA + aK) * 2;
    const unsigned bN   = (lane & 7) + ((lane >> 4) << 3);
    const unsigned bK   = ((lane >> 3) & 1) << 3;
    const unsigned bOff  = (bN * PB + bK) * 2;
    const unsigned bOff2 = ((lane & 7) * PB + (((lane >> 3) & 1) << 3)) * 2;

    auto ldA = [&](uint32_t (&f)[4][4], unsigned kaB) {
#pragma unroll
        for (int mf = 0; mf < 4; mf++)
            LDSM4(f[mf][0], f[mf][1], f[mf][2], f[mf][3],
                  aHB + mf * (16 * PA * 2) + kaB);
    };

    // =================== GEMM1: h1 = lrelu(h0 @ W1 + b1) ====================
    // warp tile 64x64, 4 k64-chunks, fragment double-buffered
    float acc[4][8][4];
#pragma unroll
    for (int mf = 0; mf < 4; mf++)
#pragma unroll
        for (int nf = 0; nf < 8; nf++)
#pragma unroll
            for (int e = 0; e < 4; e++) acc[mf][nf][e] = 0.f;

    for (int tc = 0; tc < 4; tc++) {
        CP_WAIT0();
        __syncthreads();
        if (tc < 3) loadB(g_B1 + (size_t)(tc + 1) * B1_CHUNK_HALVES, (tc + 1) & 1, B1_CHUNK_BYTES);
        else        loadB(g_B2, 0, B2_CHUNK_BYTES);   // B2 chunk0 (global parity 0)
        const unsigned bBase = smb + OFF_B + (tc & 1) * BBUF_BYTES + w * (64 * PB * 2);

        uint32_t ah[2][4][4], bf[2][4][4];
        ldA(ah[0], (unsigned)(tc * 64) * 2);
#pragma unroll
        for (int p = 0; p < 4; p++)
            LDSM4(bf[0][p][0], bf[0][p][1], bf[0][p][2], bf[0][p][3],
                  bBase + bOff + p * (16 * PB * 2));
#pragma unroll
        for (int grp = 0; grp < 4; grp++) {
            const int cur = grp & 1, nxt = cur ^ 1;
            if (grp < 3) {
                ldA(ah[nxt], (unsigned)(tc * 64 + (grp + 1) * 16) * 2);
#pragma unroll
                for (int p = 0; p < 4; p++)
                    LDSM4(bf[nxt][p][0], bf[nxt][p][1], bf[nxt][p][2], bf[nxt][p][3],
                          bBase + bOff + p * (16 * PB * 2) + (unsigned)((grp + 1) * 16) * 2);
            }
#pragma unroll
            for (int p = 0; p < 4; p++)
#pragma unroll
                for (int q = 0; q < 2; q++) {
                    int nf = 2 * p + q;
                    uint32_t bb[2] = { bf[cur][p][2 * q], bf[cur][p][2 * q + 1] };
#pragma unroll
                    for (int mf = 0; mf < 4; mf++) hmma(acc[mf][nf], ah[cur][mf], bb);
                }
        }
    }
    __syncthreads();

    // ---- h1 epilogue: bias + lrelu, fp16, overwrite A ----
    {
        const int g = lane >> 2, tig = lane & 3;
#pragma unroll
        for (int mf = 0; mf < 4; mf++) {
            int row0 = mf * 16 + g, row1 = row0 + 8;
#pragma unroll
            for (int nf = 0; nf < 8; nf++) {
                int col = w * 64 + nf * 8 + 2 * tig;
                float ba = b1s[col], bb = b1s[col + 1];
                *(__half2*)(Ah + row0 * PA + col) = __halves2half2(
                    __float2half_rn(lrelu(acc[mf][nf][0] + ba)),
                    __float2half_rn(lrelu(acc[mf][nf][1] + bb)));
                *(__half2*)(Ah + row1 * PA + col) = __halves2half2(
                    __float2half_rn(lrelu(acc[mf][nf][2] + ba)),
                    __float2half_rn(lrelu(acc[mf][nf][3] + bb)));
            }
        }
    }
    __syncthreads();

    // =================== GEMM2: h2 = lrelu(h1 @ W2 + b2) ====================
    // warp tile 64x24 (full 64 rows per warp), fragment double-buffered
    float ac2[4][3][4];
#pragma unroll
    for (int mf = 0; mf < 4; mf++)
#pragma unroll
        for (int nf = 0; nf < 3; nf++)
#pragma unroll
            for (int e = 0; e < 4; e++) ac2[mf][nf][e] = 0.f;

    for (int tc = 0; tc < 4; tc++) {
        CP_WAIT0();
        __syncthreads();
        if (tc < 3) loadB(g_B2 + (size_t)(tc + 1) * B2_CHUNK_HALVES, (tc + 1) & 1, B2_CHUNK_BYTES);
        const unsigned bBase = smb + OFF_B + (tc & 1) * BBUF_BYTES + w * (24 * PB * 2);

        uint32_t ah[2][4][4], bq[2][4], b2q[2][2];
        ldA(ah[0], (unsigned)(tc * 64) * 2);
        LDSM4(bq[0][0], bq[0][1], bq[0][2], bq[0][3], bBase + bOff);
        LDSM2(b2q[0][0], b2q[0][1], bBase + 16 * PB * 2 + bOff2);
#pragma unroll
        for (int grp = 0; grp < 4; grp++) {
            const int cur = grp & 1, nxt = cur ^ 1;
            if (grp < 3) {
                ldA(ah[nxt], (unsigned)(tc * 64 + (grp + 1) * 16) * 2);
                LDSM4(bq[nxt][0], bq[nxt][1], bq[nxt][2], bq[nxt][3],
                      bBase + bOff + (unsigned)((grp + 1) * 16) * 2);
                LDSM2(b2q[nxt][0], b2q[nxt][1],
                      bBase + 16 * PB * 2 + bOff2 + (unsigned)((grp + 1) * 16) * 2);
            }
#pragma unroll
            for (int nf = 0; nf < 3; nf++) {
                uint32_t bb[2];
                if (nf < 2) { bb[0] = bq[cur][2 * nf]; bb[1] = bq[cur][2 * nf + 1]; }
                else        { bb[0] = b2q[cur][0];     bb[1] = b2q[cur][1]; }
#pragma unroll
                for (int mf = 0; mf < 4; mf++) hmma(ac2[mf][nf], ah[cur][mf], bb);
            }
        }
    }

    // ---- reduce over j: bias+lrelu in regs, shfl over row-groups, direct store ----
    {
        const int tig = lane & 3;
        float s0[3], s1[3];
#pragma unroll
        for (int nf = 0; nf < 3; nf++) {
            int col = w * 24 + nf * 8 + 2 * tig;
            float ba = b2s[col], bb = b2s[col + 1];
            s0[nf] = 0.f; s1[nf] = 0.f;
#pragma unroll
            for (int mf = 0; mf < 4; mf++) {
                s0[nf] += lrelu(ac2[mf][nf][0] + ba) + lrelu(ac2[mf][nf][2] + ba);
                s1[nf] += lrelu(ac2[mf][nf][1] + bb) + lrelu(ac2[mf][nf][3] + bb);
            }
        }
#pragma unroll
        for (int off = 4; off <= 16; off <<= 1)
#pragma unroll
            for (int nf = 0; nf < 3; nf++) {
                s0[nf] += __shfl_xor_sync(0xffffffffu, s0[nf], off);
                s1[nf] += __shfl_xor_sync(0xffffffffu, s1[nf], off);
            }
        if (lane < 4) {
#pragma unroll
            for (int nf = 0; nf < 3; nf++) {
                int col = w * 24 + nf * 8 + 2 * lane;
                g_AGG[(size_t)node * C2 + col]     = s0[nf];
                g_AGG[(size_t)node * C2 + col + 1] = s1[nf];
            }
        }
    }
}

// ---------------- node MLP (fp32) --------------------------------------------
__global__ __launch_bounds__(256) void node_kernel(
    const float* __restrict__ x,
    const float* __restrict__ Wn0, const float* __restrict__ bn0,
    const float* __restrict__ Wn1, const float* __restrict__ bn1,
    float* __restrict__ out)
{
    __shared__ float t160[16 * 160];
    __shared__ float zs[16 * 256];
    const int r0 = blockIdx.x * 16;
    const int tid = threadIdx.x;

    for (int idx = tid; idx < 16 * 160; idx += 256) {
        int rr = idx / 160, k = idx - rr * 160;
        t160[idx] = (k < 96) ? g_AGG[(size_t)(r0 + rr) * 96 + k]
                             : x[(size_t)(r0 + rr) * 64 + (k - 96)];
    }
    __syncthreads();
    {
        const int c = tid;
        float acc[16];
        float bb = bn0[c];
#pragma unroll
        for (int r = 0; r < 16; r++) acc[r] = bb;
#pragma unroll 4
        for (int k = 0; k < 160; k++) {
            float wv = Wn0[(size_t)k * 256 + c];
#pragma unroll
            for (int r = 0; r < 16; r++) acc[r] = fmaf(t160[r * 160 + k], wv, acc[r]);
        }
#pragma unroll
        for (int r = 0; r < 16; r++) zs[r * 256 + c] = lrelu(acc[r]);
    }
    __syncthreads();
    for (int pass = 0; pass < 4; pass++) {
        int r = pass * 4 + (tid >> 6), c = tid & 63;
        float a = bn1[c];
#pragma unroll 8
        for (int k = 0; k < 256; k++)
            a = fmaf(zs[r * 256 + k], Wn1[(size_t)k * 64 + c], a);
        out[(size_t)(r0 + r) * 64 + c] = a;
    }
}

// ---------------- launch -----------------------------------------------------
extern "C" void kernel_launch(void* const* d_in, const int* in_sizes, int n_in,
                              void* d_out, int out_size)
{
    const float* x    = (const float*)d_in[0];
    const float* feW0 = (const float*)d_in[1];
    const float* feb0 = (const float*)d_in[2];
    const float* feW1 = (const float*)d_in[3];
    const float* feb1 = (const float*)d_in[4];
    const float* feW2 = (const float*)d_in[5];
    const float* feb2 = (const float*)d_in[6];
    const float* fnW0 = (const float*)d_in[7];
    const float* fnb0 = (const float*)d_in[8];
    const float* fnW1 = (const float*)d_in[9];
    const float* fnb1 = (const float*)d_in[10];
    float* out = (float*)d_out;

    cudaFuncSetAttribute(mp_main, cudaFuncAttributeMaxDynamicSharedMemorySize, SMEM_SZ);

    pq_kernel<<<512, 256>>>(x, feW0, feb0);
    dist_kernel<<<128, 256>>>(x);
    prep_w<<<352, 256>>>(feW1, feW2);
    prep_vec<<<1, 256>>>(feW0, feb1, feb2);
    mp_main<<<BATCH * NN, THREADS, SMEM_SZ>>>(x);
    node_kernel<<<512, 256>>>(x, fnW0, fnb0, fnW1, fnb1, out);
}

// round 15
// speedup vs baseline: 1.6231x; 1.0635x over previous
#include <cuda_runtime.h>
#include <cuda_fp16.h>
#include <cstdint>

#define BATCH 128
#define NN    64
#define C1    256
#define C2    96
#define PA    264         // A smem pitch in halves (528B, conflict-free)
#define PB    72          // B1 smem pitch in halves (144B, conflict-free)
#define PB2   136         // B2 smem pitch in halves (272B, conflict-free)
#define THREADS 128

// ---------------- global scratch ---------------------------------------------
__device__ float  g_P[BATCH * NN * C1];
__device__ float  g_Q[BATCH * NN * C1];
__device__ __half g_B1[4 * 256 * PB];       // [kchunk64][n=256][k=72pad]
__device__ __half g_B2[2 * 96 * PB2];       // [kchunk128][n=96][k=136pad]
__device__ float  g_DIST[BATCH * NN * 64];
__device__ float  g_AGG[BATCH * NN * C2];
__device__ float  g_vec[C1 + C1 + 128];     // w0d | b1 | b2

__device__ __forceinline__ float lrelu(float v) { return v > 0.f ? v : 0.2f * v; }

#define CP_ASYNC16(smaddr, gptr) \
    asm volatile("cp.async.cg.shared.global [%0], [%1], 16;" :: "r"(smaddr), "l"(gptr))
#define CP_COMMIT() asm volatile("cp.async.commit_group;")
#define CP_WAIT0()  asm volatile("cp.async.wait_group 0;" ::: "memory")

__device__ __forceinline__ void hmma(float* c, const uint32_t* a, const uint32_t* b) {
    asm volatile(
        "mma.sync.aligned.m16n8k16.row.col.f32.f16.f16.f32 "
        "{%0,%1,%2,%3}, {%4,%5,%6,%7}, {%8,%9}, {%0,%1,%2,%3};"
        : "+f"(c[0]), "+f"(c[1]), "+f"(c[2]), "+f"(c[3])
        : "r"(a[0]), "r"(a[1]), "r"(a[2]), "r"(a[3]), "r"(b[0]), "r"(b[1]));
}

#define LDSM4(R0, R1, R2, R3, ADDR) \
    asm volatile("ldmatrix.sync.aligned.m8n8.x4.shared.b16 {%0,%1,%2,%3}, [%4];" \
        : "=r"(R0), "=r"(R1), "=r"(R2), "=r"(R3) : "r"(ADDR))
#define LDSM2(R0, R1, ADDR) \
    asm volatile("ldmatrix.sync.aligned.m8n8.x2.shared.b16 {%0,%1}, [%2];" \
        : "=r"(R0), "=r"(R1) : "r"(ADDR))

// ---------------- fused prep kernel (one launch, 993 blocks) -----------------
// blocks [0,512): P/Q  | [512,640): dist | [640,992): weight pack | 992: vectors
__global__ __launch_bounds__(256) void prep_all(
    const float* __restrict__ x,  const float* __restrict__ W0,
    const float* __restrict__ b0, const float* __restrict__ W1,
    const float* __restrict__ W2, const float* __restrict__ b1,
    const float* __restrict__ b2)
{
    const int blk = blockIdx.x;
    const int tid = threadIdx.x;

    if (blk < 512) {                                    // ---- P/Q precompute
        __shared__ float xs[16 * 64];
        const int r0 = blk * 16;
        ((float4*)xs)[tid] = ((const float4*)(x + (size_t)r0 * 64))[tid];
        __syncthreads();
        const int c = tid;
        float accP[16], accQ[16];
#pragma unroll
        for (int r = 0; r < 16; r++) { accP[r] = 0.f; accQ[r] = 0.f; }
#pragma unroll 4
        for (int f = 0; f < 64; f++) {
            float wp = W0[f * C1 + c];
            float wq = W0[(64 + f) * C1 + c];
#pragma unroll
            for (int r = 0; r < 16; r++) {
                float xv = xs[r * 64 + f];
                accP[r] = fmaf(xv, wp, accP[r]);
                accQ[r] = fmaf(xv, wq, accQ[r]);
            }
        }
        float bias = b0[c];
#pragma unroll
        for (int r = 0; r < 16; r++) {
            g_P[(size_t)(r0 + r) * C1 + c] = accP[r] + bias;
            g_Q[(size_t)(r0 + r) * C1 + c] = accQ[r];
        }
    } else if (blk < 640) {                             // ---- all-pairs dist
        __shared__ float xs[64 * 64];
        const int b = blk - 512;
        for (int t = tid; t < 1024; t += 256)
            ((float4*)xs)[t] = ((const float4*)(x + (size_t)b * 4096))[t];
        __syncthreads();
        for (int p = tid; p < 4096; p += 256) {
            int i = p >> 6, j = p & 63;
            float s = 0.f;
#pragma unroll
            for (int f = 0; f < 64; f++) {
                float d = xs[j * 64 + f] - xs[i * 64 + f] + 1e-12f;
                s = fmaf(d, d, s);
            }
            g_DIST[((size_t)b * 64 + i) * 64 + j] = sqrtf(s);
        }
    } else if (blk < 992) {                             // ---- weight pack
        int idx = (blk - 640) * 256 + tid;
        if (idx < 65536) {                  // B1: 4 chunks x 256 n x 64 k
            int t = idx >> 14, rem = idx & 16383;
            int n = rem >> 6, k = rem & 63;
            g_B1[(size_t)(t * 256 + n) * PB + k] =
                __float2half_rn(W1[(size_t)(t * 64 + k) * C1 + n]);
        } else if (idx - 65536 < 24576) {   // B2: 2 chunks x 96 n x 128 k
            int p = idx - 65536;
            int t = p / 12288, rem = p % 12288;
            int n = rem >> 7, kl = rem & 127;
            g_B2[(size_t)(t * 96 + n) * PB2 + kl] =
                __float2half_rn(W2[(size_t)(t * 128 + kl) * C2 + n]);
        }
    } else {                                            // ---- small vectors
        g_vec[tid] = W0[128 * C1 + tid];
        g_vec[C1 + tid] = b1[tid];
        if (tid < C2) g_vec[2 * C1 + tid] = b2[tid];
    }
}

// ---------------- main mma.sync kernel (1 node / CTA, 2 CTAs per SM) ---------
#define B1_CHUNK_HALVES (256 * PB)          // 18432
#define B1_CHUNK_BYTES  (B1_CHUNK_HALVES * 2)   // 36864
#define B2_CHUNK_HALVES (96 * PB2)          // 13056
#define B2_CHUNK_BYTES  (B2_CHUNK_HALVES * 2)   // 26112
#define BBUF_BYTES      36864
#define OFF_A    0                          // 64 x 264 halves = 33792
#define OFF_B    33792                      // 2 x 36864 = 73728
#define OFF_PV   107520                     // 1024
#define OFF_W0   108544                     // 1024
#define OFF_B1S  109568                     // 1024
#define OFF_B2S  110592                     // 512
#define OFF_DIST 111104                     // 256
#define SMEM_SZ  111360

__global__ void __launch_bounds__(THREADS, 2) mp_main(const float* __restrict__ x)
{
    extern __shared__ __align__(16) unsigned char sm[];
    const unsigned smb = (unsigned)__cvta_generic_to_shared(sm);
    const int tid = threadIdx.x;
    const int w = tid >> 5, lane = tid & 31;
    const int node = blockIdx.x;
    const int b = node >> 6;

    __half* Ah  = (__half*)(sm + OFF_A);
    float* pv   = (float*)(sm + OFF_PV);
    float* w0s  = (float*)(sm + OFF_W0);
    float* b1s  = (float*)(sm + OFF_B1S);
    float* b2s  = (float*)(sm + OFF_B2S);
    float* dst_ = (float*)(sm + OFF_DIST);

    auto loadB = [&](const __half* gsrc, int dstbuf, int bytes) {
        unsigned sb = smb + OFF_B + dstbuf * BBUF_BYTES;
        const char* gp = (const char*)gsrc;
        for (int q = tid * 16; q < bytes; q += THREADS * 16)
            CP_ASYNC16(sb + q, gp + q);
        CP_COMMIT();
    };

    // issue first B1 chunk immediately (overlaps with staging + h0 build)
    loadB(g_B1, 0, B1_CHUNK_BYTES);

    // ---- stage small vectors + dist ----
    {
        pv[tid]        = g_P[(size_t)node * C1 + tid];
        pv[tid + 128]  = g_P[(size_t)node * C1 + tid + 128];
        w0s[tid]       = g_vec[tid];
        w0s[tid + 128] = g_vec[tid + 128];
        b1s[tid]       = g_vec[C1 + tid];
        b1s[tid + 128] = g_vec[C1 + tid + 128];
        if (tid < C2) b2s[tid] = g_vec[2 * C1 + tid];
        if (tid < 64) dst_[tid] = g_DIST[(size_t)node * 64 + tid];
    }
    __syncthreads();

    // ---- build h0 fp16: 64 x 256 (each thread: half a row) ----
    {
        int r = tid >> 1, kq = (tid & 1) * 128;
        float dj = dst_[r];
        const float4* q4 = (const float4*)(g_Q + ((size_t)(b * 64 + r)) * 256);
        __half2* ahp = (__half2*)(Ah + r * PA);
#pragma unroll
        for (int g4 = 0; g4 < 32; g4++) {
            int k = kq + g4 * 4;
            float4 q = q4[k >> 2];
            float v0 = lrelu(pv[k + 0] + q.x + dj * w0s[k + 0]);
            float v1 = lrelu(pv[k + 1] + q.y + dj * w0s[k + 1]);
            float v2 = lrelu(pv[k + 2] + q.z + dj * w0s[k + 2]);
            float v3 = lrelu(pv[k + 3] + q.w + dj * w0s[k + 3]);
            ahp[(k >> 1) + 0] = __halves2half2(__float2half_rn(v0), __float2half_rn(v1));
            ahp[(k >> 1) + 1] = __halves2half2(__float2half_rn(v2), __float2half_rn(v3));
        }
    }

    // ---- ldmatrix lane address components (bytes) ----
    const unsigned aRow = lane & 15;
    const unsigned aK   = (lane >> 4) << 3;
    const unsigned aHB  = smb + OFF_A + (aRow * PA + aK) * 2;
    const unsigned bN   = (lane & 7) + ((lane >> 4) << 3);
    const unsigned bK   = ((lane >> 3) & 1) << 3;
    const unsigned bOff   = (bN * PB + bK) * 2;
    const unsigned bOffB2  = (bN * PB2 + bK) * 2;
    const unsigned bOff2B2 = ((lane & 7) * PB2 + (((lane >> 3) & 1) << 3)) * 2;

    auto ldA = [&](uint32_t (&f)[4][4], unsigned kaB) {
#pragma unroll
        for (int mf = 0; mf < 4; mf++)
            LDSM4(f[mf][0], f[mf][1], f[mf][2], f[mf][3],
                  aHB + mf * (16 * PA * 2) + kaB);
    };

    // =================== GEMM1: h1 = lrelu(h0 @ W1 + b1) ====================
    // warp tile 64x64, 4 k64-chunks, fragment double-buffered
    float acc[4][8][4];
#pragma unroll
    for (int mf = 0; mf < 4; mf++)
#pragma unroll
        for (int nf = 0; nf < 8; nf++)
#pragma unroll
            for (int e = 0; e < 4; e++) acc[mf][nf][e] = 0.f;

    for (int tc = 0; tc < 4; tc++) {
        CP_WAIT0();
        __syncthreads();
        if (tc < 3) loadB(g_B1 + (size_t)(tc + 1) * B1_CHUNK_HALVES, (tc + 1) & 1, B1_CHUNK_BYTES);
        else        loadB(g_B2, 0, B2_CHUNK_BYTES);   // B2 chunk0 into buf0
        const unsigned bBase = smb + OFF_B + (tc & 1) * BBUF_BYTES + w * (64 * PB * 2);

        uint32_t ah[2][4][4], bf[2][4][4];
        ldA(ah[0], (unsigned)(tc * 64) * 2);
#pragma unroll
        for (int p = 0; p < 4; p++)
            LDSM4(bf[0][p][0], bf[0][p][1], bf[0][p][2], bf[0][p][3],
                  bBase + bOff + p * (16 * PB * 2));
#pragma unroll
        for (int grp = 0; grp < 4; grp++) {
            const int cur = grp & 1, nxt = cur ^ 1;
            if (grp < 3) {
                ldA(ah[nxt], (unsigned)(tc * 64 + (grp + 1) * 16) * 2);
#pragma unroll
                for (int p = 0; p < 4; p++)
                    LDSM4(bf[nxt][p][0], bf[nxt][p][1], bf[nxt][p][2], bf[nxt][p][3],
                          bBase + bOff + p * (16 * PB * 2) + (unsigned)((grp + 1) * 16) * 2);
            }
#pragma unroll
            for (int p = 0; p < 4; p++)
#pragma unroll
                for (int q = 0; q < 2; q++) {
                    int nf = 2 * p + q;
                    uint32_t bb[2] = { bf[cur][p][2 * q], bf[cur][p][2 * q + 1] };
#pragma unroll
                    for (int mf = 0; mf < 4; mf++) hmma(acc[mf][nf], ah[cur][mf], bb);
                }
        }
    }
    __syncthreads();

    // ---- h1 epilogue: bias + lrelu, fp16, overwrite A ----
    {
        const int g = lane >> 2, tig = lane & 3;
#pragma unroll
        for (int mf = 0; mf < 4; mf++) {
            int row0 = mf * 16 + g, row1 = row0 + 8;
#pragma unroll
            for (int nf = 0; nf < 8; nf++) {
                int col = w * 64 + nf * 8 + 2 * tig;
                float ba = b1s[col], bb = b1s[col + 1];
                *(__half2*)(Ah + row0 * PA + col) = __halves2half2(
                    __float2half_rn(lrelu(acc[mf][nf][0] + ba)),
                    __float2half_rn(lrelu(acc[mf][nf][1] + bb)));
                *(__half2*)(Ah + row1 * PA + col) = __halves2half2(
                    __float2half_rn(lrelu(acc[mf][nf][2] + ba)),
                    __float2half_rn(lrelu(acc[mf][nf][3] + bb)));
            }
        }
    }
    __syncthreads();

    // =================== GEMM2: h2 = lrelu(h1 @ W2 + b2) ====================
    // warp tile 64x24, 2 k128-chunks, fragment double-buffered
    float ac2[4][3][4];
#pragma unroll
    for (int mf = 0; mf < 4; mf++)
#pragma unroll
        for (int nf = 0; nf < 3; nf++)
#pragma unroll
            for (int e = 0; e < 4; e++) ac2[mf][nf][e] = 0.f;

    for (int tc = 0; tc < 2; tc++) {
        CP_WAIT0();
        __syncthreads();
        if (tc == 0) loadB(g_B2 + (size_t)B2_CHUNK_HALVES, 1, B2_CHUNK_BYTES);
        const unsigned bBase = smb + OFF_B + tc * BBUF_BYTES + w * (24 * PB2 * 2);

        uint32_t ah[2][4][4], bq[2][4], b2q[2][2];
        ldA(ah[0], (unsigned)(tc * 128) * 2);
        LDSM4(bq[0][0], bq[0][1], bq[0][2], bq[0][3], bBase + bOffB2);
        LDSM2(b2q[0][0], b2q[0][1], bBase + 16 * PB2 * 2 + bOff2B2);
#pragma unroll
        for (int grp = 0; grp < 8; grp++) {
            const int cur = grp & 1, nxt = cur ^ 1;
            if (grp < 7) {
                ldA(ah[nxt], (unsigned)(tc * 128 + (grp + 1) * 16) * 2);
                LDSM4(bq[nxt][0], bq[nxt][1], bq[nxt][2], bq[nxt][3],
                      bBase + bOffB2 + (unsigned)((grp + 1) * 16) * 2);
                LDSM2(b2q[nxt][0], b2q[nxt][1],
                      bBase + 16 * PB2 * 2 + bOff2B2 + (unsigned)((grp + 1) * 16) * 2);
            }
#pragma unroll
            for (int nf = 0; nf < 3; nf++) {
                uint32_t bb[2];
                if (nf < 2) { bb[0] = bq[cur][2 * nf]; bb[1] = bq[cur][2 * nf + 1]; }
                else        { bb[0] = b2q[cur][0];     bb[1] = b2q[cur][1]; }
#pragma unroll
                for (int mf = 0; mf < 4; mf++) hmma(ac2[mf][nf], ah[cur][mf], bb);
            }
        }
    }

    // ---- reduce over j: bias+lrelu in regs, shfl over row-groups, direct store ----
    {
        const int tig = lane & 3;
        float s0[3], s1[3];
#pragma unroll
        for (int nf = 0; nf < 3; nf++) {
            int col = w * 24 + nf * 8 + 2 * tig;
            float ba = b2s[col], bb = b2s[col + 1];
            s0[nf] = 0.f; s1[nf] = 0.f;
#pragma unroll
            for (int mf = 0; mf < 4; mf++) {
                s0[nf] += lrelu(ac2[mf][nf][0] + ba) + lrelu(ac2[mf][nf][2] + ba);
                s1[nf] += lrelu(ac2[mf][nf][1] + bb) + lrelu(ac2[mf][nf][3] + bb);
            }
        }
#pragma unroll
        for (int off = 4; off <= 16; off <<= 1)
#pragma unroll
            for (int nf = 0; nf < 3; nf++) {
                s0[nf] += __shfl_xor_sync(0xffffffffu, s0[nf], off);
                s1[nf] += __shfl_xor_sync(0xffffffffu, s1[nf], off);
            }
        if (lane < 4) {
#pragma unroll
            for (int nf = 0; nf < 3; nf++) {
                int col = w * 24 + nf * 8 + 2 * lane;
                g_AGG[(size_t)node * C2 + col]     = s0[nf];
                g_AGG[(size_t)node * C2 + col + 1] = s1[nf];
            }
        }
    }
}

// ---------------- node MLP (fp32) --------------------------------------------
__global__ __launch_bounds__(256) void node_kernel(
    const float* __restrict__ x,
    const float* __restrict__ Wn0, const float* __restrict__ bn0,
    const float* __restrict__ Wn1, const float* __restrict__ bn1,
    float* __restrict__ out)
{
    __shared__ float t160[16 * 160];
    __shared__ float zs[16 * 256];
    const int r0 = blockIdx.x * 16;
    const int tid = threadIdx.x;

    for (int idx = tid; idx < 16 * 160; idx += 256) {
        int rr = idx / 160, k = idx - rr * 160;
        t160[idx] = (k < 96) ? g_AGG[(size_t)(r0 + rr) * 96 + k]
                             : x[(size_t)(r0 + rr) * 64 + (k - 96)];
    }
    __syncthreads();
    {
        const int c = tid;
        float acc[16];
        float bb = bn0[c];
#pragma unroll
        for (int r = 0; r < 16; r++) acc[r] = bb;
#pragma unroll 4
        for (int k = 0; k < 160; k++) {
            float wv = Wn0[(size_t)k * 256 + c];
#pragma unroll
            for (int r = 0; r < 16; r++) acc[r] = fmaf(t160[r * 160 + k], wv, acc[r]);
        }
#pragma unroll
        for (int r = 0; r < 16; r++) zs[r * 256 + c] = lrelu(acc[r]);
    }
    __syncthreads();
    for (int pass = 0; pass < 4; pass++) {
        int r = pass * 4 + (tid >> 6), c = tid & 63;
        float a = bn1[c];
#pragma unroll 8
        for (int k = 0; k < 256; k++)
            a = fmaf(zs[r * 256 + k], Wn1[(size_t)k * 64 + c], a);
        out[(size_t)(r0 + r) * 64 + c] = a;
    }
}

// ---------------- launch -----------------------------------------------------
extern "C" void kernel_launch(void* const* d_in, const int* in_sizes, int n_in,
                              void* d_out, int out_size)
{
    const float* x    = (const float*)d_in[0];
    const float* feW0 = (const float*)d_in[1];
    const float* feb0 = (const float*)d_in[2];
    const float* feW1 = (const float*)d_in[3];
    const float* feb1 = (const float*)d_in[4];
    const float* feW2 = (const float*)d_in[5];
    const float* feb2 = (const float*)d_in[6];
    const float* fnW0 = (const float*)d_in[7];
    const float* fnb0 = (const float*)d_in[8];
    const float* fnW1 = (const float*)d_in[9];
    const float* fnb1 = (const float*)d_in[10];
    float* out = (float*)d_out;

    cudaFuncSetAttribute(mp_main, cudaFuncAttributeMaxDynamicSharedMemorySize, SMEM_SZ);

    prep_all<<<993, 256>>>(x, feW0, feb0, feW1, feW2, feb1, feb2);
    mp_main<<<BATCH * NN, THREADS, SMEM_SZ>>>(x);
    node_kernel<<<512, 256>>>(x, fnW0, fnb0, fnW1, fnb1, out);
}